// round 1
// baseline (speedup 1.0000x reference)
#include <cuda_runtime.h>
#include <math.h>

#define DIMC 768
#define NH 12
#define HD 64
#define NB 8
#define NT 1024
#define M_TOK (NB*NT)   // 8192

// ---- scratch (device globals: no allocations allowed) ----
__device__ float g_q[NB*NH*NT*HD];          // 25 MB, [b,h,n,d]
__device__ float g_k[NB*NH*NT*HD];
__device__ float g_v[NB*NH*NT*HD];
__device__ float g_S[(size_t)NB*NH*NT*NT];  // 402 MB scores (in-place mixed probs)
__device__ float g_O[(size_t)M_TOK*DIMC];   // 25 MB, [tok, dim]

// ============================================================
// Generic SGEMM: C = scale * (A @ B) (+bias). A: MxK row-major,
// B: KxN row-major. Tile 128x128x8, 256 threads, 8x8 microtile.
// head_split=1 writes C into [b,h,row,d] layout (N must be 768).
// ============================================================
__global__ __launch_bounds__(256) void sgemm_nn(
    const float* __restrict__ A, const float* __restrict__ Bm,
    float* __restrict__ C, const float* __restrict__ bias,
    int M, int Nn, int K, float scale, int head_split)
{
    __shared__ float As[8][128];
    __shared__ float Bs[8][128];
    int tid = threadIdx.x;
    int rowBase = blockIdx.y * 128;
    int colBase = blockIdx.x * 128;
    int ty = tid >> 4, tx = tid & 15;
    int arow = tid >> 1, ac = (tid & 1) * 4;
    int brow = tid >> 5, bc = (tid & 31) * 4;
    float acc[8][8] = {};

    for (int k0 = 0; k0 < K; k0 += 8) {
        float4 av = *(const float4*)&A[(size_t)(rowBase + arow) * K + k0 + ac];
        As[ac+0][arow] = av.x; As[ac+1][arow] = av.y;
        As[ac+2][arow] = av.z; As[ac+3][arow] = av.w;
        *(float4*)&Bs[brow][bc] =
            *(const float4*)&Bm[(size_t)(k0 + brow) * Nn + colBase + bc];
        __syncthreads();
#pragma unroll
        for (int kk = 0; kk < 8; kk++) {
            float4 a0 = *(const float4*)&As[kk][ty*8];
            float4 a1 = *(const float4*)&As[kk][ty*8+4];
            float4 b0 = *(const float4*)&Bs[kk][tx*8];
            float4 b1 = *(const float4*)&Bs[kk][tx*8+4];
            float a[8] = {a0.x,a0.y,a0.z,a0.w,a1.x,a1.y,a1.z,a1.w};
            float bb[8] = {b0.x,b0.y,b0.z,b0.w,b1.x,b1.y,b1.z,b1.w};
#pragma unroll
            for (int i = 0; i < 8; i++)
#pragma unroll
                for (int j = 0; j < 8; j++)
                    acc[i][j] = fmaf(a[i], bb[j], acc[i][j]);
        }
        __syncthreads();
    }

    int col0 = colBase + tx*8;
    float bvals[8] = {};
    if (bias) {
#pragma unroll
        for (int j = 0; j < 8; j++) bvals[j] = bias[col0 + j];
    }
#pragma unroll
    for (int i = 0; i < 8; i++) {
        int m = rowBase + ty*8 + i;
        float v[8];
#pragma unroll
        for (int j = 0; j < 8; j++) v[j] = acc[i][j]*scale + bvals[j];
        float4 v0 = make_float4(v[0],v[1],v[2],v[3]);
        float4 v1 = make_float4(v[4],v[5],v[6],v[7]);
        if (head_split) {
            int b_ = m >> 10, r = m & 1023;
            int h  = col0 >> 6, d = col0 & 63;
            float* dst = C + (((size_t)(b_*NH + h) * NT + r) * HD + d);
            *(float4*)dst = v0;
            *(float4*)(dst + 4) = v1;
        } else {
            float* dst = C + (size_t)m * Nn + col0;
            *(float4*)dst = v0;
            *(float4*)(dst + 4) = v1;
        }
    }
}

// ============================================================
// Scores: per (b,h): S = Q (1024x64) @ K^T. Tile 128x128, K=64.
// ============================================================
__global__ __launch_bounds__(256) void score_kernel(
    const float* __restrict__ Q, const float* __restrict__ Kp,
    float* __restrict__ S)
{
    __shared__ float As[8][128];
    __shared__ float Bs[8][128];
    int bh = blockIdx.z;
    const float* A  = Q  + (size_t)bh * (NT*HD);
    const float* Bp = Kp + (size_t)bh * (NT*HD);
    float* C = S + (size_t)bh * NT * NT;

    int tid = threadIdx.x;
    int rowBase = blockIdx.y * 128, colBase = blockIdx.x * 128;
    int ty = tid >> 4, tx = tid & 15;
    int arow = tid >> 1, ac = (tid & 1) * 4;
    float acc[8][8] = {};

    for (int k0 = 0; k0 < HD; k0 += 8) {
        float4 av = *(const float4*)&A[(size_t)(rowBase + arow) * HD + k0 + ac];
        As[ac+0][arow] = av.x; As[ac+1][arow] = av.y;
        As[ac+2][arow] = av.z; As[ac+3][arow] = av.w;
        float4 bv = *(const float4*)&Bp[(size_t)(colBase + arow) * HD + k0 + ac];
        Bs[ac+0][arow] = bv.x; Bs[ac+1][arow] = bv.y;
        Bs[ac+2][arow] = bv.z; Bs[ac+3][arow] = bv.w;
        __syncthreads();
#pragma unroll
        for (int kk = 0; kk < 8; kk++) {
            float4 a0 = *(const float4*)&As[kk][ty*8];
            float4 a1 = *(const float4*)&As[kk][ty*8+4];
            float4 b0 = *(const float4*)&Bs[kk][tx*8];
            float4 b1 = *(const float4*)&Bs[kk][tx*8+4];
            float a[8] = {a0.x,a0.y,a0.z,a0.w,a1.x,a1.y,a1.z,a1.w};
            float bb[8] = {b0.x,b0.y,b0.z,b0.w,b1.x,b1.y,b1.z,b1.w};
#pragma unroll
            for (int i = 0; i < 8; i++)
#pragma unroll
                for (int j = 0; j < 8; j++)
                    acc[i][j] = fmaf(a[i], bb[j], acc[i][j]);
        }
        __syncthreads();
    }
#pragma unroll
    for (int i = 0; i < 8; i++) {
        float* dst = C + (size_t)(rowBase + ty*8 + i) * NT + colBase + tx*8;
        *(float4*)dst     = make_float4(acc[i][0],acc[i][1],acc[i][2],acc[i][3]);
        *(float4*)(dst+4) = make_float4(acc[i][4],acc[i][5],acc[i][6],acc[i][7]);
    }
}

// ============================================================
// Fused talking-heads: per (b, query-row i):
//   load raw S[b,:,i,:] (12x1024) -> pre-mix (Wl,bl) -> softmax per
//   head -> post-mix (Ww,bw) -> write back in place.
// 384 threads = 12 warps, 1 warp per head for the softmax.
// ============================================================
__global__ __launch_bounds__(384) void softmax_mix_kernel(
    float* __restrict__ S, const float* __restrict__ Wl,
    const float* __restrict__ bl, const float* __restrict__ Ww,
    const float* __restrict__ bw)
{
    extern __shared__ float sm[];
    float* buf = sm;            // 12*1024
    float* wl  = sm + 12288;    // 144
    float* ww  = wl + 144;      // 144
    float* blv = ww + 144;      // 12
    float* bwv = blv + 12;      // 12

    int tid = threadIdx.x;
    int i = blockIdx.x, b = blockIdx.y;
    if (tid < 144)                    wl[tid]      = Wl[tid];
    if (tid >= 160 && tid < 304)      ww[tid-160]  = Ww[tid-160];
    if (tid >= 320 && tid < 332)      blv[tid-320] = bl[tid-320];
    if (tid >= 352 && tid < 364)      bwv[tid-352] = bw[tid-352];

    size_t rowbase = (size_t)b * NH * NT * NT + (size_t)i * NT;  // + h*NT*NT
    for (int idx = tid; idx < NH*NT; idx += 384)
        buf[idx] = S[rowbase + (size_t)(idx >> 10) * (NT*NT) + (idx & 1023)];
    __syncthreads();

    // pre-softmax head mix (in place; each thread owns distinct j columns)
    for (int j = tid; j < NT; j += 384) {
        float s[12];
#pragma unroll
        for (int h = 0; h < 12; h++) s[h] = buf[h*1024 + j];
#pragma unroll
        for (int g = 0; g < 12; g++) {
            float m = blv[g];
#pragma unroll
            for (int h = 0; h < 12; h++) m = fmaf(wl[g*12+h], s[h], m);
            buf[g*1024 + j] = m;
        }
    }
    __syncthreads();

    // per-head softmax: warp w handles head w
    {
        int w = tid >> 5, lane = tid & 31;
        float* row = buf + w * 1024;
        float mx = -1e30f;
        for (int j = lane; j < 1024; j += 32) mx = fmaxf(mx, row[j]);
#pragma unroll
        for (int o = 16; o; o >>= 1) mx = fmaxf(mx, __shfl_xor_sync(0xffffffffu, mx, o));
        float sum = 0.f;
        float e[32];
        int t = 0;
        for (int j = lane; j < 1024; j += 32, t++) {
            float ev = __expf(row[j] - mx);
            e[t] = ev; sum += ev;
        }
#pragma unroll
        for (int o = 16; o; o >>= 1) sum += __shfl_xor_sync(0xffffffffu, sum, o);
        float rinv = 1.f / sum;
        t = 0;
        for (int j = lane; j < 1024; j += 32, t++) row[j] = e[t] * rinv;
    }
    __syncthreads();

    // post-softmax head mix + write back
    for (int j = tid; j < NT; j += 384) {
        float p[12];
#pragma unroll
        for (int h = 0; h < 12; h++) p[h] = buf[h*1024 + j];
#pragma unroll
        for (int g = 0; g < 12; g++) {
            float m = bwv[g];
#pragma unroll
            for (int h = 0; h < 12; h++) m = fmaf(ww[g*12+h], p[h], m);
            S[rowbase + (size_t)g * (NT*NT) + j] = m;
        }
    }
}

// ============================================================
// AV: per (b,h): O(1024x64) = P(1024x1024) @ V(1024x64).
// Writes O in plain [tok, dim] layout for the final projection.
// Tile 128x64x8, 256 threads, 8x4 microtile.
// ============================================================
__global__ __launch_bounds__(256) void av_kernel(
    const float* __restrict__ P, const float* __restrict__ V,
    float* __restrict__ O)
{
    __shared__ float As[8][128];
    __shared__ float Bs[8][64];
    int bh = blockIdx.y;
    int b = bh / NH, h = bh % NH;
    const float* A  = P + (size_t)bh * NT * NT + (size_t)blockIdx.x * 128 * NT;
    const float* Bp = V + (size_t)bh * NT * HD;

    int tid = threadIdx.x;
    int ty = tid >> 4, tx = tid & 15;
    int arow = tid >> 1, ac = (tid & 1) * 4;
    float acc[8][4] = {};

    for (int k0 = 0; k0 < NT; k0 += 8) {
        float4 av = *(const float4*)&A[(size_t)arow * NT + k0 + ac];
        As[ac+0][arow] = av.x; As[ac+1][arow] = av.y;
        As[ac+2][arow] = av.z; As[ac+3][arow] = av.w;
        if (tid < 128) {
            int brow = tid >> 4, bc2 = (tid & 15) * 4;
            *(float4*)&Bs[brow][bc2] =
                *(const float4*)&Bp[(size_t)(k0 + brow) * HD + bc2];
        }
        __syncthreads();
#pragma unroll
        for (int kk = 0; kk < 8; kk++) {
            float4 a0 = *(const float4*)&As[kk][ty*8];
            float4 a1 = *(const float4*)&As[kk][ty*8+4];
            float4 bv = *(const float4*)&Bs[kk][tx*4];
            float a[8]  = {a0.x,a0.y,a0.z,a0.w,a1.x,a1.y,a1.z,a1.w};
            float bb[4] = {bv.x,bv.y,bv.z,bv.w};
#pragma unroll
            for (int i = 0; i < 8; i++)
#pragma unroll
                for (int j = 0; j < 4; j++)
                    acc[i][j] = fmaf(a[i], bb[j], acc[i][j]);
        }
        __syncthreads();
    }
#pragma unroll
    for (int i = 0; i < 8; i++) {
        int row = blockIdx.x*128 + ty*8 + i;
        float* dst = O + (size_t)(b*NT + row) * DIMC + h*HD + tx*4;
        *(float4*)dst = make_float4(acc[i][0],acc[i][1],acc[i][2],acc[i][3]);
    }
}

// ============================================================
extern "C" void kernel_launch(void* const* d_in, const int* in_sizes, int n_in,
                              void* d_out, int out_size)
{
    const float* x  = (const float*)d_in[0];
    const float* Wq = (const float*)d_in[1];
    const float* Wk = (const float*)d_in[2];
    const float* Wv = (const float*)d_in[3];
    const float* Wl = (const float*)d_in[4];
    const float* bl = (const float*)d_in[5];
    const float* Ww = (const float*)d_in[6];
    const float* bw = (const float*)d_in[7];
    const float* Wp = (const float*)d_in[8];
    const float* bp = (const float*)d_in[9];
    float* out = (float*)d_out;

    float *gq, *gk, *gv, *gS, *gO;
    cudaGetSymbolAddress((void**)&gq, g_q);
    cudaGetSymbolAddress((void**)&gk, g_k);
    cudaGetSymbolAddress((void**)&gv, g_v);
    cudaGetSymbolAddress((void**)&gS, g_S);
    cudaGetSymbolAddress((void**)&gO, g_O);

    const float scale = 0.125f;  // HD^-0.5

    // QKV projections -> [b,h,n,d]; Q pre-scaled
    sgemm_nn<<<dim3(6,64), 256>>>(x, Wq, gq, nullptr, M_TOK, DIMC, DIMC, scale, 1);
    sgemm_nn<<<dim3(6,64), 256>>>(x, Wk, gk, nullptr, M_TOK, DIMC, DIMC, 1.0f, 1);
    sgemm_nn<<<dim3(6,64), 256>>>(x, Wv, gv, nullptr, M_TOK, DIMC, DIMC, 1.0f, 1);

    // raw scores S = Q K^T  (96 batched GEMMs)
    score_kernel<<<dim3(8,8,96), 256>>>(gq, gk, gS);

    // fused pre-mix + softmax + post-mix (in place on gS)
    int smbytes = (12*1024 + 144 + 144 + 12 + 12) * (int)sizeof(float);
    cudaFuncSetAttribute(softmax_mix_kernel,
                         cudaFuncAttributeMaxDynamicSharedMemorySize, smbytes);
    softmax_mix_kernel<<<dim3(1024, 8), 384, smbytes>>>(gS, Wl, bl, Ww, bw);

    // attn @ V -> plain [tok, dim] layout
    av_kernel<<<dim3(8, 96), 256>>>(gS, gv, gO);

    // final projection + bias
    sgemm_nn<<<dim3(6,64), 256>>>(gO, Wp, out, bp, M_TOK, DIMC, DIMC, 1.0f, 0);
}

// round 2
// speedup vs baseline: 1.8626x; 1.8626x over previous
#include <cuda_runtime.h>
#include <math.h>

#define DIMC 768
#define NH 12
#define HD 64
#define NB 8
#define NT 1024
#define M_TOK (NB*NT)   // 8192

// ---- scratch (device globals: no allocations allowed) ----
__device__ float g_q[NB*NH*NT*HD];          // [b,h,n,d], Q pre-scaled
__device__ float g_k[NB*NH*NT*HD];
__device__ float g_v[NB*NH*NT*HD];
__device__ float g_S[(size_t)NB*NH*NT*NT];  // 402 MB scores / probs (in place)
__device__ float g_O[(size_t)M_TOK*DIMC];   // [tok, dim]

// ---------- tf32 helpers ----------
__device__ __forceinline__ unsigned f2tf(float f) {
    unsigned u; asm("cvt.rna.tf32.f32 %0, %1;" : "=r"(u) : "f"(f)); return u;
}
__device__ __forceinline__ void mma8(float* d, unsigned a0, unsigned a1,
                                     unsigned a2, unsigned a3,
                                     unsigned b0, unsigned b1) {
    asm volatile(
        "mma.sync.aligned.m16n8k8.row.col.f32.tf32.tf32.f32 "
        "{%0,%1,%2,%3},{%4,%5,%6,%7},{%8,%9},{%0,%1,%2,%3};"
        : "+f"(d[0]), "+f"(d[1]), "+f"(d[2]), "+f"(d[3])
        : "r"(a0), "r"(a1), "r"(a2), "r"(a3), "r"(b0), "r"(b1));
}

// ============================================================
// proj_tf32: C[M,768] = scale*(A[M,768] @ B[768,768]) (+bias)
// Block tile 128x128, kstep 32. 256 thr, warp grid 2(m)x4(n),
// warp tile 64x32. head_split writes [b,h,n,d].
// ============================================================
__global__ __launch_bounds__(256) void proj_tf32(
    const float* __restrict__ A, const float* __restrict__ Bm,
    float* __restrict__ C, const float* __restrict__ bias,
    float scale, int head_split)
{
    __shared__ float As[128][36];   // [m][k], stride 36 -> frag bank = 4m+k (CF)
    __shared__ float Bs[32][136];   // [k][n], stride 136 -> frag bank = 8k+n (CF)
    const int K = DIMC, Nn = DIMC;
    int tid = threadIdx.x, lane = tid & 31, wid = tid >> 5;
    int warp_m = wid & 1, warp_n = wid >> 1;
    int rowBase = blockIdx.y * 128, colBase = blockIdx.x * 128;
    int lr = lane >> 2, lc = lane & 3;

    int ar = tid >> 1, ac = (tid & 1) * 16;       // A stage: 4 float4 along k
    int br = tid >> 3, bc = (tid & 7) * 16;       // B stage: 4 float4 along n

    const float* Aptr = A + (size_t)(rowBase + ar) * K + ac;
    const float* Bptr = Bm + (size_t)br * Nn + colBase + bc;

    float4 aReg[4], bReg[4];
#pragma unroll
    for (int i = 0; i < 4; i++) aReg[i] = *(const float4*)(Aptr + i * 4);
#pragma unroll
    for (int i = 0; i < 4; i++) bReg[i] = *(const float4*)(Bptr + i * 4);

    float acc[4][4][4] = {};
    int m0 = warp_m * 64, n0 = warp_n * 32;

    for (int k0 = 0; k0 < K; k0 += 32) {
#pragma unroll
        for (int i = 0; i < 4; i++) {
            float4 v = aReg[i];
            As[ar][ac + i*4 + 0] = __uint_as_float(f2tf(v.x));
            As[ar][ac + i*4 + 1] = __uint_as_float(f2tf(v.y));
            As[ar][ac + i*4 + 2] = __uint_as_float(f2tf(v.z));
            As[ar][ac + i*4 + 3] = __uint_as_float(f2tf(v.w));
        }
#pragma unroll
        for (int i = 0; i < 4; i++) {
            float4 v = bReg[i];
            Bs[br][bc + i*4 + 0] = __uint_as_float(f2tf(v.x));
            Bs[br][bc + i*4 + 1] = __uint_as_float(f2tf(v.y));
            Bs[br][bc + i*4 + 2] = __uint_as_float(f2tf(v.z));
            Bs[br][bc + i*4 + 3] = __uint_as_float(f2tf(v.w));
        }
        __syncthreads();
        if (k0 + 32 < K) {
            Aptr += 32;
            Bptr += (size_t)32 * Nn;
#pragma unroll
            for (int i = 0; i < 4; i++) aReg[i] = *(const float4*)(Aptr + i * 4);
#pragma unroll
            for (int i = 0; i < 4; i++) bReg[i] = *(const float4*)(Bptr + i * 4);
        }
#pragma unroll
        for (int kk = 0; kk < 32; kk += 8) {
            unsigned a[4][4], b[4][2];
#pragma unroll
            for (int mi = 0; mi < 4; mi++) {
                int r = m0 + mi * 16 + lr;
                a[mi][0] = __float_as_uint(As[r    ][kk + lc]);
                a[mi][1] = __float_as_uint(As[r + 8][kk + lc]);
                a[mi][2] = __float_as_uint(As[r    ][kk + lc + 4]);
                a[mi][3] = __float_as_uint(As[r + 8][kk + lc + 4]);
            }
#pragma unroll
            for (int ni = 0; ni < 4; ni++) {
                int c = n0 + ni * 8 + lr;
                b[ni][0] = __float_as_uint(Bs[kk + lc    ][c]);
                b[ni][1] = __float_as_uint(Bs[kk + lc + 4][c]);
            }
#pragma unroll
            for (int mi = 0; mi < 4; mi++)
#pragma unroll
                for (int ni = 0; ni < 4; ni++)
                    mma8(acc[mi][ni], a[mi][0], a[mi][1], a[mi][2], a[mi][3],
                         b[ni][0], b[ni][1]);
        }
        __syncthreads();
    }

#pragma unroll
    for (int mi = 0; mi < 4; mi++) {
#pragma unroll
        for (int ni = 0; ni < 4; ni++) {
            int col = colBase + n0 + ni * 8 + 2 * lc;
            float bv0 = 0.f, bv1 = 0.f;
            if (bias) { bv0 = bias[col]; bv1 = bias[col + 1]; }
#pragma unroll
            for (int half = 0; half < 2; half++) {
                int row = rowBase + m0 + mi * 16 + lr + half * 8;
                float2 v = make_float2(acc[mi][ni][half*2 + 0] * scale + bv0,
                                       acc[mi][ni][half*2 + 1] * scale + bv1);
                if (head_split) {
                    int b_ = row >> 10, rr = row & 1023;
                    int h = col >> 6, d = col & 63;
                    *(float2*)&C[(((size_t)(b_ * NH + h) * NT + rr) * HD + d)] = v;
                } else {
                    *(float2*)&C[(size_t)row * Nn + col] = v;
                }
            }
        }
    }
}

// ============================================================
// score_tf32: per (b,h): S = Q(1024x64) @ K^T. 128x128 tile,
// whole K=64 resident in smem. Dynamic smem 2*128*68*4 B.
// ============================================================
__global__ __launch_bounds__(256) void score_tf32(
    const float* __restrict__ Q, const float* __restrict__ Kp,
    float* __restrict__ S)
{
    extern __shared__ float sm[];
    float (*Qs)[68] = (float(*)[68])sm;
    float (*Ks)[68] = (float(*)[68])(sm + 128 * 68);

    int bh = blockIdx.z;
    const float* Qg = Q + (size_t)bh * NT * HD + (size_t)blockIdx.y * 128 * HD;
    const float* Kg = Kp + (size_t)bh * NT * HD + (size_t)blockIdx.x * 128 * HD;

    int tid = threadIdx.x, lane = tid & 31, wid = tid >> 5;
    int lr = lane >> 2, lc = lane & 3;
    int warp_m = wid & 1, warp_n = wid >> 1;

    int row = tid >> 4, col4 = (tid & 15) * 4;
#pragma unroll
    for (int it = 0; it < 8; it++) {
        int r = it * 16 + row;
        float4 v = *(const float4*)(Qg + (size_t)r * HD + col4);
        Qs[r][col4+0] = __uint_as_float(f2tf(v.x));
        Qs[r][col4+1] = __uint_as_float(f2tf(v.y));
        Qs[r][col4+2] = __uint_as_float(f2tf(v.z));
        Qs[r][col4+3] = __uint_as_float(f2tf(v.w));
        float4 w = *(const float4*)(Kg + (size_t)r * HD + col4);
        Ks[r][col4+0] = __uint_as_float(f2tf(w.x));
        Ks[r][col4+1] = __uint_as_float(f2tf(w.y));
        Ks[r][col4+2] = __uint_as_float(f2tf(w.z));
        Ks[r][col4+3] = __uint_as_float(f2tf(w.w));
    }
    __syncthreads();

    float acc[4][4][4] = {};
    int m0 = warp_m * 64, n0 = warp_n * 32;
#pragma unroll
    for (int kk = 0; kk < 64; kk += 8) {
        unsigned a[4][4], b[4][2];
#pragma unroll
        for (int mi = 0; mi < 4; mi++) {
            int r = m0 + mi * 16 + lr;
            a[mi][0] = __float_as_uint(Qs[r    ][kk + lc]);
            a[mi][1] = __float_as_uint(Qs[r + 8][kk + lc]);
            a[mi][2] = __float_as_uint(Qs[r    ][kk + lc + 4]);
            a[mi][3] = __float_as_uint(Qs[r + 8][kk + lc + 4]);
        }
#pragma unroll
        for (int ni = 0; ni < 4; ni++) {
            int c = n0 + ni * 8 + lr;
            b[ni][0] = __float_as_uint(Ks[c][kk + lc]);
            b[ni][1] = __float_as_uint(Ks[c][kk + lc + 4]);
        }
#pragma unroll
        for (int mi = 0; mi < 4; mi++)
#pragma unroll
            for (int ni = 0; ni < 4; ni++)
                mma8(acc[mi][ni], a[mi][0], a[mi][1], a[mi][2], a[mi][3],
                     b[ni][0], b[ni][1]);
    }

    float* Sg = S + (size_t)bh * NT * NT;
#pragma unroll
    for (int mi = 0; mi < 4; mi++) {
#pragma unroll
        for (int ni = 0; ni < 4; ni++) {
            int c = blockIdx.x * 128 + n0 + ni * 8 + 2 * lc;
#pragma unroll
            for (int half = 0; half < 2; half++) {
                int r = blockIdx.y * 128 + m0 + mi * 16 + lr + half * 8;
                *(float2*)&Sg[(size_t)r * NT + c] =
                    make_float2(acc[mi][ni][half*2], acc[mi][ni][half*2 + 1]);
            }
        }
    }
}

// ============================================================
// Fused talking-heads softmax (unchanged from round 1)
// ============================================================
__global__ __launch_bounds__(384) void softmax_mix_kernel(
    float* __restrict__ S, const float* __restrict__ Wl,
    const float* __restrict__ bl, const float* __restrict__ Ww,
    const float* __restrict__ bw)
{
    extern __shared__ float sm[];
    float* buf = sm;
    float* wl  = sm + 12288;
    float* ww  = wl + 144;
    float* blv = ww + 144;
    float* bwv = blv + 12;

    int tid = threadIdx.x;
    int i = blockIdx.x, b = blockIdx.y;
    if (tid < 144)               wl[tid]       = Wl[tid];
    if (tid >= 160 && tid < 304) ww[tid - 160] = Ww[tid - 160];
    if (tid >= 320 && tid < 332) blv[tid - 320] = bl[tid - 320];
    if (tid >= 352 && tid < 364) bwv[tid - 352] = bw[tid - 352];

    size_t rowbase = (size_t)b * NH * NT * NT + (size_t)i * NT;
    for (int idx = tid; idx < NH * NT; idx += 384)
        buf[idx] = S[rowbase + (size_t)(idx >> 10) * (NT * NT) + (idx & 1023)];
    __syncthreads();

    for (int j = tid; j < NT; j += 384) {
        float s[12];
#pragma unroll
        for (int h = 0; h < 12; h++) s[h] = buf[h * 1024 + j];
#pragma unroll
        for (int g = 0; g < 12; g++) {
            float m = blv[g];
#pragma unroll
            for (int h = 0; h < 12; h++) m = fmaf(wl[g * 12 + h], s[h], m);
            buf[g * 1024 + j] = m;
        }
    }
    __syncthreads();

    {
        int w = tid >> 5, lane = tid & 31;
        float* row = buf + w * 1024;
        float mx = -1e30f;
        for (int j = lane; j < 1024; j += 32) mx = fmaxf(mx, row[j]);
#pragma unroll
        for (int o = 16; o; o >>= 1) mx = fmaxf(mx, __shfl_xor_sync(0xffffffffu, mx, o));
        float sum = 0.f;
        float e[32];
        int t = 0;
        for (int j = lane; j < 1024; j += 32, t++) {
            float ev = __expf(row[j] - mx);
            e[t] = ev; sum += ev;
        }
#pragma unroll
        for (int o = 16; o; o >>= 1) sum += __shfl_xor_sync(0xffffffffu, sum, o);
        float rinv = 1.f / sum;
        t = 0;
        for (int j = lane; j < 1024; j += 32, t++) row[j] = e[t] * rinv;
    }
    __syncthreads();

    for (int j = tid; j < NT; j += 384) {
        float p[12];
#pragma unroll
        for (int h = 0; h < 12; h++) p[h] = buf[h * 1024 + j];
#pragma unroll
        for (int g = 0; g < 12; g++) {
            float m = bwv[g];
#pragma unroll
            for (int h = 0; h < 12; h++) m = fmaf(ww[g * 12 + h], p[h], m);
            S[rowbase + (size_t)g * (NT * NT) + j] = m;
        }
    }
}

// ============================================================
// av_tf32: per (b,h): O(1024x64) = P(1024x1024) @ V(1024x64).
// Block 128x64, kstep 32, 256 thr, warp grid 4(m)x2(n), warp 32x32.
// ============================================================
__global__ __launch_bounds__(256) void av_tf32(
    const float* __restrict__ P, const float* __restrict__ V,
    float* __restrict__ O)
{
    __shared__ float Ps[128][36];   // [m][k]
    __shared__ float Vs[32][72];    // [k][n], stride 72 -> frag bank 8k+n (CF)
    int bh = blockIdx.y;
    int b = bh / NH, h = bh % NH;
    const float* Pg = P + (size_t)bh * NT * NT + (size_t)blockIdx.x * 128 * NT;
    const float* Vg = V + (size_t)bh * NT * HD;

    int tid = threadIdx.x, lane = tid & 31, wid = tid >> 5;
    int lr = lane >> 2, lc = lane & 3;
    int warp_m = wid & 3, warp_n = wid >> 2;

    int pr = tid >> 1, pc = (tid & 1) * 16;
    int vr = tid >> 3, vc = (tid & 7) * 8;

    const float* Pp = Pg + (size_t)pr * NT + pc;
    const float* Vp = Vg + (size_t)vr * HD + vc;

    float4 pReg[4], vReg[2];
#pragma unroll
    for (int i = 0; i < 4; i++) pReg[i] = *(const float4*)(Pp + i * 4);
#pragma unroll
    for (int i = 0; i < 2; i++) vReg[i] = *(const float4*)(Vp + i * 4);

    float acc[2][4][4] = {};
    int m0 = warp_m * 32, n0 = warp_n * 32;

    for (int k0 = 0; k0 < NT; k0 += 32) {
#pragma unroll
        for (int i = 0; i < 4; i++) {
            float4 v = pReg[i];
            Ps[pr][pc + i*4 + 0] = __uint_as_float(f2tf(v.x));
            Ps[pr][pc + i*4 + 1] = __uint_as_float(f2tf(v.y));
            Ps[pr][pc + i*4 + 2] = __uint_as_float(f2tf(v.z));
            Ps[pr][pc + i*4 + 3] = __uint_as_float(f2tf(v.w));
        }
#pragma unroll
        for (int i = 0; i < 2; i++) {
            float4 v = vReg[i];
            Vs[vr][vc + i*4 + 0] = __uint_as_float(f2tf(v.x));
            Vs[vr][vc + i*4 + 1] = __uint_as_float(f2tf(v.y));
            Vs[vr][vc + i*4 + 2] = __uint_as_float(f2tf(v.z));
            Vs[vr][vc + i*4 + 3] = __uint_as_float(f2tf(v.w));
        }
        __syncthreads();
        if (k0 + 32 < NT) {
            Pp += 32;
            Vp += (size_t)32 * HD;
#pragma unroll
            for (int i = 0; i < 4; i++) pReg[i] = *(const float4*)(Pp + i * 4);
#pragma unroll
            for (int i = 0; i < 2; i++) vReg[i] = *(const float4*)(Vp + i * 4);
        }
#pragma unroll
        for (int kk = 0; kk < 32; kk += 8) {
            unsigned a[2][4], bfr[4][2];
#pragma unroll
            for (int mi = 0; mi < 2; mi++) {
                int r = m0 + mi * 16 + lr;
                a[mi][0] = __float_as_uint(Ps[r    ][kk + lc]);
                a[mi][1] = __float_as_uint(Ps[r + 8][kk + lc]);
                a[mi][2] = __float_as_uint(Ps[r    ][kk + lc + 4]);
                a[mi][3] = __float_as_uint(Ps[r + 8][kk + lc + 4]);
            }
#pragma unroll
            for (int ni = 0; ni < 4; ni++) {
                int c = n0 + ni * 8 + lr;
                bfr[ni][0] = __float_as_uint(Vs[kk + lc    ][c]);
                bfr[ni][1] = __float_as_uint(Vs[kk + lc + 4][c]);
            }
#pragma unroll
            for (int mi = 0; mi < 2; mi++)
#pragma unroll
                for (int ni = 0; ni < 4; ni++)
                    mma8(acc[mi][ni], a[mi][0], a[mi][1], a[mi][2], a[mi][3],
                         bfr[ni][0], bfr[ni][1]);
        }
        __syncthreads();
    }

#pragma unroll
    for (int mi = 0; mi < 2; mi++) {
#pragma unroll
        for (int ni = 0; ni < 4; ni++) {
            int col = n0 + ni * 8 + 2 * lc;
#pragma unroll
            for (int half = 0; half < 2; half++) {
                int row = blockIdx.x * 128 + m0 + mi * 16 + lr + half * 8;
                *(float2*)&O[(size_t)(b * NT + row) * DIMC + h * HD + col] =
                    make_float2(acc[mi][ni][half*2], acc[mi][ni][half*2 + 1]);
            }
        }
    }
}

// ============================================================
extern "C" void kernel_launch(void* const* d_in, const int* in_sizes, int n_in,
                              void* d_out, int out_size)
{
    const float* x  = (const float*)d_in[0];
    const float* Wq = (const float*)d_in[1];
    const float* Wk = (const float*)d_in[2];
    const float* Wv = (const float*)d_in[3];
    const float* Wl = (const float*)d_in[4];
    const float* bl = (const float*)d_in[5];
    const float* Ww = (const float*)d_in[6];
    const float* bw = (const float*)d_in[7];
    const float* Wp = (const float*)d_in[8];
    const float* bp = (const float*)d_in[9];
    float* out = (float*)d_out;

    float *gq, *gk, *gv, *gS, *gO;
    cudaGetSymbolAddress((void**)&gq, g_q);
    cudaGetSymbolAddress((void**)&gk, g_k);
    cudaGetSymbolAddress((void**)&gv, g_v);
    cudaGetSymbolAddress((void**)&gS, g_S);
    cudaGetSymbolAddress((void**)&gO, g_O);

    const float scale = 0.125f;  // HD^-0.5

    // QKV projections -> [b,h,n,d]; Q pre-scaled
    proj_tf32<<<dim3(6, 64), 256>>>(x, Wq, gq, nullptr, scale, 1);
    proj_tf32<<<dim3(6, 64), 256>>>(x, Wk, gk, nullptr, 1.0f, 1);
    proj_tf32<<<dim3(6, 64), 256>>>(x, Wv, gv, nullptr, 1.0f, 1);

    // raw scores S = Q K^T
    int score_smem = 2 * 128 * 68 * (int)sizeof(float);
    cudaFuncSetAttribute(score_tf32,
                         cudaFuncAttributeMaxDynamicSharedMemorySize, score_smem);
    score_tf32<<<dim3(8, 8, 96), 256, score_smem>>>(gq, gk, gS);

    // fused pre-mix + softmax + post-mix (in place on gS)
    int smbytes = (12 * 1024 + 144 + 144 + 12 + 12) * (int)sizeof(float);
    cudaFuncSetAttribute(softmax_mix_kernel,
                         cudaFuncAttributeMaxDynamicSharedMemorySize, smbytes);
    softmax_mix_kernel<<<dim3(1024, 8), 384, smbytes>>>(gS, Wl, bl, Ww, bw);

    // attn @ V -> [tok, dim]
    av_tf32<<<dim3(8, 96), 256>>>(gS, gv, gO);

    // final projection + bias
    proj_tf32<<<dim3(6, 64), 256>>>(gO, Wp, out, bp, 1.0f, 0);
}

// round 3
// speedup vs baseline: 2.8676x; 1.5395x over previous
#include <cuda_runtime.h>
#include <math.h>

#define DIMC 768
#define NH 12
#define HD 64
#define NB 8
#define NT 1024
#define M_TOK (NB*NT)   // 8192

// ---- scratch (device globals: no allocations allowed) ----
__device__ float g_q[NB*NH*NT*HD];          // [b,h,n,d], Q pre-scaled
__device__ float g_k[NB*NH*NT*HD];
__device__ float g_v[NB*NH*NT*HD];
__device__ float g_S[(size_t)NB*NH*NT*NT];  // 402 MB scores / probs (in place)
__device__ float g_O[(size_t)M_TOK*DIMC];   // [tok, dim]

// ---------- helpers ----------
__device__ __forceinline__ unsigned f2tf(float f) {
    unsigned u; asm("cvt.rna.tf32.f32 %0, %1;" : "=r"(u) : "f"(f)); return u;
}
__device__ __forceinline__ unsigned ld_tf(const float* p) {
    return f2tf(*p);
}
__device__ __forceinline__ void mma8(float* d, unsigned a0, unsigned a1,
                                     unsigned a2, unsigned a3,
                                     unsigned b0, unsigned b1) {
    asm volatile(
        "mma.sync.aligned.m16n8k8.row.col.f32.tf32.tf32.f32 "
        "{%0,%1,%2,%3},{%4,%5,%6,%7},{%8,%9},{%0,%1,%2,%3};"
        : "+f"(d[0]), "+f"(d[1]), "+f"(d[2]), "+f"(d[3])
        : "r"(a0), "r"(a1), "r"(a2), "r"(a3), "r"(b0), "r"(b1));
}
__device__ __forceinline__ void cp16(void* s, const void* g) {
    unsigned sa = (unsigned)__cvta_generic_to_shared(s);
    asm volatile("cp.async.ca.shared.global [%0], [%1], 16;" :: "r"(sa), "l"(g));
}
#define CP_COMMIT asm volatile("cp.async.commit_group;")
#define CP_WAIT1  asm volatile("cp.async.wait_group 1;")

// ============================================================
// proj_tf32: C[8192,768] = scale*(A @ B[768,768]) (+bias)
// 128x128 tile, BK=16, 3-stage cp.async pipeline, 256 thr,
// warp grid 2(m)x4(n), warp tile 64x32. smem holds raw fp32;
// tf32 cvt at fragment load.
// ============================================================
__global__ __launch_bounds__(256, 2) void proj_tf32(
    const float* __restrict__ A, const float* __restrict__ Bm,
    float* __restrict__ C, const float* __restrict__ bias,
    float scale, int head_split)
{
    extern __shared__ float sm[];
    float* As = sm;               // [3][128][20]
    float* Bs = sm + 3 * 2560;    // [3][16][136]

    int tid = threadIdx.x, lane = tid & 31, wid = tid >> 5;
    int warp_m = wid & 1, warp_n = wid >> 1;
    int rowBase = blockIdx.y * 128, colBase = blockIdx.x * 128;
    int lr = lane >> 2, lc = lane & 3;
    int m0 = warp_m * 64, n0 = warp_n * 32;

    const float* Ap = A + (size_t)rowBase * DIMC;
    const float* Bp = Bm + colBase;

#define PROJ_LOAD(s, k0) do {                                          \
    float* Ad = As + (s) * 2560;                                       \
    float* Bd = Bs + (s) * 2176;                                       \
    _Pragma("unroll")                                                  \
    for (int i_ = 0; i_ < 2; i_++) {                                   \
        int t_ = tid + i_ * 256;                                       \
        int r_ = t_ >> 2, c_ = (t_ & 3) * 4;                           \
        cp16(&Ad[r_ * 20 + c_], Ap + (size_t)r_ * DIMC + (k0) + c_);   \
        int br_ = t_ >> 5, bc_ = (t_ & 31) * 4;                        \
        cp16(&Bd[br_ * 136 + bc_], Bp + (size_t)((k0) + br_) * DIMC + bc_); \
    }                                                                  \
    CP_COMMIT;                                                         \
} while (0)

    PROJ_LOAD(0, 0);
    PROJ_LOAD(1, 16);

    float acc[4][4][4] = {};
    const int NITER = DIMC / 16;   // 48
    for (int it = 0; it < NITER; it++) {
        CP_WAIT1;
        __syncthreads();
        int s = it % 3;
        const float* Aq = As + s * 2560;
        const float* Bq = Bs + s * 2176;
#pragma unroll
        for (int kk = 0; kk < 16; kk += 8) {
            unsigned a[4][4], b[4][2];
#pragma unroll
            for (int mi = 0; mi < 4; mi++) {
                int r = m0 + mi * 16 + lr;
                a[mi][0] = ld_tf(&Aq[r * 20 + kk + lc]);
                a[mi][1] = ld_tf(&Aq[(r + 8) * 20 + kk + lc]);
                a[mi][2] = ld_tf(&Aq[r * 20 + kk + lc + 4]);
                a[mi][3] = ld_tf(&Aq[(r + 8) * 20 + kk + lc + 4]);
            }
#pragma unroll
            for (int ni = 0; ni < 4; ni++) {
                int c = n0 + ni * 8 + lr;
                b[ni][0] = ld_tf(&Bq[(kk + lc) * 136 + c]);
                b[ni][1] = ld_tf(&Bq[(kk + lc + 4) * 136 + c]);
            }
#pragma unroll
            for (int mi = 0; mi < 4; mi++)
#pragma unroll
                for (int ni = 0; ni < 4; ni++)
                    mma8(acc[mi][ni], a[mi][0], a[mi][1], a[mi][2], a[mi][3],
                         b[ni][0], b[ni][1]);
        }
        __syncthreads();
        if (it + 2 < NITER) PROJ_LOAD((it + 2) % 3, (it + 2) * 16);
        else CP_COMMIT;
    }
#undef PROJ_LOAD

#pragma unroll
    for (int mi = 0; mi < 4; mi++) {
#pragma unroll
        for (int ni = 0; ni < 4; ni++) {
            int col = colBase + n0 + ni * 8 + 2 * lc;
            float bv0 = 0.f, bv1 = 0.f;
            if (bias) { bv0 = bias[col]; bv1 = bias[col + 1]; }
#pragma unroll
            for (int half = 0; half < 2; half++) {
                int row = rowBase + m0 + mi * 16 + lr + half * 8;
                float2 v = make_float2(acc[mi][ni][half*2 + 0] * scale + bv0,
                                       acc[mi][ni][half*2 + 1] * scale + bv1);
                if (head_split) {
                    int b_ = row >> 10, rr = row & 1023;
                    int h = col >> 6, d = col & 63;
                    *(float2*)&C[(((size_t)(b_ * NH + h) * NT + rr) * HD + d)] = v;
                } else {
                    *(float2*)&C[(size_t)row * DIMC + col] = v;
                }
            }
        }
    }
}

// ============================================================
// score_tf32: per (b,h): S = Q(1024x64) @ K^T. 128x128 tile,
// whole K=64 resident in smem (tf32 stored once).
// ============================================================
__global__ __launch_bounds__(256, 2) void score_tf32(
    const float* __restrict__ Q, const float* __restrict__ Kp,
    float* __restrict__ S)
{
    extern __shared__ float sm[];
    float (*Qs)[68] = (float(*)[68])sm;
    float (*Ks)[68] = (float(*)[68])(sm + 128 * 68);

    int bh = blockIdx.z;
    const float* Qg = Q + (size_t)bh * NT * HD + (size_t)blockIdx.y * 128 * HD;
    const float* Kg = Kp + (size_t)bh * NT * HD + (size_t)blockIdx.x * 128 * HD;

    int tid = threadIdx.x, lane = tid & 31, wid = tid >> 5;
    int lr = lane >> 2, lc = lane & 3;
    int warp_m = wid & 1, warp_n = wid >> 1;

    int row = tid >> 4, col4 = (tid & 15) * 4;
#pragma unroll
    for (int it = 0; it < 8; it++) {
        int r = it * 16 + row;
        float4 v = *(const float4*)(Qg + (size_t)r * HD + col4);
        Qs[r][col4+0] = __uint_as_float(f2tf(v.x));
        Qs[r][col4+1] = __uint_as_float(f2tf(v.y));
        Qs[r][col4+2] = __uint_as_float(f2tf(v.z));
        Qs[r][col4+3] = __uint_as_float(f2tf(v.w));
        float4 w = *(const float4*)(Kg + (size_t)r * HD + col4);
        Ks[r][col4+0] = __uint_as_float(f2tf(w.x));
        Ks[r][col4+1] = __uint_as_float(f2tf(w.y));
        Ks[r][col4+2] = __uint_as_float(f2tf(w.z));
        Ks[r][col4+3] = __uint_as_float(f2tf(w.w));
    }
    __syncthreads();

    float acc[4][4][4] = {};
    int m0 = warp_m * 64, n0 = warp_n * 32;
#pragma unroll
    for (int kk = 0; kk < 64; kk += 8) {
        unsigned a[4][4], b[4][2];
#pragma unroll
        for (int mi = 0; mi < 4; mi++) {
            int r = m0 + mi * 16 + lr;
            a[mi][0] = __float_as_uint(Qs[r    ][kk + lc]);
            a[mi][1] = __float_as_uint(Qs[r + 8][kk + lc]);
            a[mi][2] = __float_as_uint(Qs[r    ][kk + lc + 4]);
            a[mi][3] = __float_as_uint(Qs[r + 8][kk + lc + 4]);
        }
#pragma unroll
        for (int ni = 0; ni < 4; ni++) {
            int c = n0 + ni * 8 + lr;
            b[ni][0] = __float_as_uint(Ks[c][kk + lc]);
            b[ni][1] = __float_as_uint(Ks[c][kk + lc + 4]);
        }
#pragma unroll
        for (int mi = 0; mi < 4; mi++)
#pragma unroll
            for (int ni = 0; ni < 4; ni++)
                mma8(acc[mi][ni], a[mi][0], a[mi][1], a[mi][2], a[mi][3],
                     b[ni][0], b[ni][1]);
    }

    float* Sg = S + (size_t)bh * NT * NT;
#pragma unroll
    for (int mi = 0; mi < 4; mi++) {
#pragma unroll
        for (int ni = 0; ni < 4; ni++) {
            int c = blockIdx.x * 128 + n0 + ni * 8 + 2 * lc;
#pragma unroll
            for (int half = 0; half < 2; half++) {
                int r = blockIdx.y * 128 + m0 + mi * 16 + lr + half * 8;
                *(float2*)&Sg[(size_t)r * NT + c] =
                    make_float2(acc[mi][ni][half*2], acc[mi][ni][half*2 + 1]);
            }
        }
    }
}

// ============================================================
// Fused talking-heads softmax; float4 global access.
// ============================================================
__global__ __launch_bounds__(384) void softmax_mix_kernel(
    float* __restrict__ S, const float* __restrict__ Wl,
    const float* __restrict__ bl, const float* __restrict__ Ww,
    const float* __restrict__ bw)
{
    extern __shared__ float sm[];
    float* buf = sm;
    float* wl  = sm + 12288;
    float* ww  = wl + 144;
    float* blv = ww + 144;
    float* bwv = blv + 12;

    int tid = threadIdx.x;
    int i = blockIdx.x, b = blockIdx.y;
    if (tid < 144)               wl[tid]       = Wl[tid];
    if (tid >= 160 && tid < 304) ww[tid - 160] = Ww[tid - 160];
    if (tid >= 320 && tid < 332) blv[tid - 320] = bl[tid - 320];
    if (tid >= 352 && tid < 364) bwv[tid - 352] = bw[tid - 352];

    size_t rowbase = (size_t)b * NH * NT * NT + (size_t)i * NT;
    for (int t = tid; t < 3072; t += 384) {
        int h = t >> 8, j4 = (t & 255) * 4;
        *(float4*)&buf[h * 1024 + j4] =
            *(const float4*)&S[rowbase + (size_t)h * (NT * NT) + j4];
    }
    __syncthreads();

    for (int j = tid; j < NT; j += 384) {
        float s[12];
#pragma unroll
        for (int h = 0; h < 12; h++) s[h] = buf[h * 1024 + j];
#pragma unroll
        for (int g = 0; g < 12; g++) {
            float m = blv[g];
#pragma unroll
            for (int h = 0; h < 12; h++) m = fmaf(wl[g * 12 + h], s[h], m);
            buf[g * 1024 + j] = m;
        }
    }
    __syncthreads();

    {
        int w = tid >> 5, lane = tid & 31;
        float* row = buf + w * 1024;
        float mx = -1e30f;
        for (int j = lane; j < 1024; j += 32) mx = fmaxf(mx, row[j]);
#pragma unroll
        for (int o = 16; o; o >>= 1) mx = fmaxf(mx, __shfl_xor_sync(0xffffffffu, mx, o));
        float sum = 0.f;
        float e[32];
        int t = 0;
        for (int j = lane; j < 1024; j += 32, t++) {
            float ev = __expf(row[j] - mx);
            e[t] = ev; sum += ev;
        }
#pragma unroll
        for (int o = 16; o; o >>= 1) sum += __shfl_xor_sync(0xffffffffu, sum, o);
        float rinv = 1.f / sum;
        t = 0;
        for (int j = lane; j < 1024; j += 32, t++) row[j] = e[t] * rinv;
    }
    __syncthreads();

    // post-mix in place (each thread owns column j)
    for (int j = tid; j < NT; j += 384) {
        float p[12];
#pragma unroll
        for (int h = 0; h < 12; h++) p[h] = buf[h * 1024 + j];
#pragma unroll
        for (int g = 0; g < 12; g++) {
            float m = bwv[g];
#pragma unroll
            for (int h = 0; h < 12; h++) m = fmaf(ww[g * 12 + h], p[h], m);
            buf[g * 1024 + j] = m;
        }
    }
    __syncthreads();

    for (int t = tid; t < 3072; t += 384) {
        int g = t >> 8, j4 = (t & 255) * 4;
        *(float4*)&S[rowbase + (size_t)g * (NT * NT) + j4] =
            *(const float4*)&buf[g * 1024 + j4];
    }
}

// ============================================================
// av_tf32: per (b,h): O(1024x64) = P(1024x1024) @ V(1024x64).
// 128x64 tile, BK=32, 3-stage cp.async, warp grid 4(m)x2(n).
// ============================================================
__global__ __launch_bounds__(256, 2) void av_tf32(
    const float* __restrict__ P, const float* __restrict__ V,
    float* __restrict__ O)
{
    extern __shared__ float sm[];
    float* Ps = sm;                // [3][128][36]
    float* Vs = sm + 3 * 4608;     // [3][32][72]

    int bh = blockIdx.y;
    int b = bh / NH, h = bh % NH;
    const float* Pg = P + (size_t)bh * NT * NT + (size_t)blockIdx.x * 128 * NT;
    const float* Vg = V + (size_t)bh * NT * HD;

    int tid = threadIdx.x, lane = tid & 31, wid = tid >> 5;
    int lr = lane >> 2, lc = lane & 3;
    int warp_m = wid & 3, warp_n = wid >> 2;
    int m0 = warp_m * 32, n0 = warp_n * 32;

#define AV_LOAD(s, k0) do {                                            \
    float* Pd = Ps + (s) * 4608;                                       \
    float* Vd = Vs + (s) * 2304;                                       \
    _Pragma("unroll")                                                  \
    for (int i_ = 0; i_ < 4; i_++) {                                   \
        int t_ = tid + i_ * 256;                                       \
        int r_ = t_ >> 3, c_ = (t_ & 7) * 4;                           \
        cp16(&Pd[r_ * 36 + c_], Pg + (size_t)r_ * NT + (k0) + c_);     \
    }                                                                  \
    _Pragma("unroll")                                                  \
    for (int i_ = 0; i_ < 2; i_++) {                                   \
        int t_ = tid + i_ * 256;                                       \
        int vr_ = t_ >> 4, vc_ = (t_ & 15) * 4;                        \
        cp16(&Vd[vr_ * 72 + vc_], Vg + (size_t)((k0) + vr_) * HD + vc_); \
    }                                                                  \
    CP_COMMIT;                                                         \
} while (0)

    AV_LOAD(0, 0);
    AV_LOAD(1, 32);

    float acc[2][4][4] = {};
    const int NITER = NT / 32;   // 32
    for (int it = 0; it < NITER; it++) {
        CP_WAIT1;
        __syncthreads();
        int s = it % 3;
        const float* Pq = Ps + s * 4608;
        const float* Vq = Vs + s * 2304;
#pragma unroll
        for (int kk = 0; kk < 32; kk += 8) {
            unsigned a[2][4], bfr[4][2];
#pragma unroll
            for (int mi = 0; mi < 2; mi++) {
                int r = m0 + mi * 16 + lr;
                a[mi][0] = ld_tf(&Pq[r * 36 + kk + lc]);
                a[mi][1] = ld_tf(&Pq[(r + 8) * 36 + kk + lc]);
                a[mi][2] = ld_tf(&Pq[r * 36 + kk + lc + 4]);
                a[mi][3] = ld_tf(&Pq[(r + 8) * 36 + kk + lc + 4]);
            }
#pragma unroll
            for (int ni = 0; ni < 4; ni++) {
                int c = n0 + ni * 8 + lr;
                bfr[ni][0] = ld_tf(&Vq[(kk + lc) * 72 + c]);
                bfr[ni][1] = ld_tf(&Vq[(kk + lc + 4) * 72 + c]);
            }
#pragma unroll
            for (int mi = 0; mi < 2; mi++)
#pragma unroll
                for (int ni = 0; ni < 4; ni++)
                    mma8(acc[mi][ni], a[mi][0], a[mi][1], a[mi][2], a[mi][3],
                         bfr[ni][0], bfr[ni][1]);
        }
        __syncthreads();
        if (it + 2 < NITER) AV_LOAD((it + 2) % 3, (it + 2) * 32);
        else CP_COMMIT;
    }
#undef AV_LOAD

#pragma unroll
    for (int mi = 0; mi < 2; mi++) {
#pragma unroll
        for (int ni = 0; ni < 4; ni++) {
            int col = n0 + ni * 8 + 2 * lc;
#pragma unroll
            for (int half = 0; half < 2; half++) {
                int row = blockIdx.x * 128 + m0 + mi * 16 + lr + half * 8;
                *(float2*)&O[(size_t)(b * NT + row) * DIMC + h * HD + col] =
                    make_float2(acc[mi][ni][half*2], acc[mi][ni][half*2 + 1]);
            }
        }
    }
}

// ============================================================
extern "C" void kernel_launch(void* const* d_in, const int* in_sizes, int n_in,
                              void* d_out, int out_size)
{
    const float* x  = (const float*)d_in[0];
    const float* Wq = (const float*)d_in[1];
    const float* Wk = (const float*)d_in[2];
    const float* Wv = (const float*)d_in[3];
    const float* Wl = (const float*)d_in[4];
    const float* bl = (const float*)d_in[5];
    const float* Ww = (const float*)d_in[6];
    const float* bw = (const float*)d_in[7];
    const float* Wp = (const float*)d_in[8];
    const float* bp = (const float*)d_in[9];
    float* out = (float*)d_out;

    float *gq, *gk, *gv, *gS, *gO;
    cudaGetSymbolAddress((void**)&gq, g_q);
    cudaGetSymbolAddress((void**)&gk, g_k);
    cudaGetSymbolAddress((void**)&gv, g_v);
    cudaGetSymbolAddress((void**)&gS, g_S);
    cudaGetSymbolAddress((void**)&gO, g_O);

    const float scale = 0.125f;  // HD^-0.5

    int proj_smem = 3 * (128*20 + 16*136) * (int)sizeof(float);      // 56832
    cudaFuncSetAttribute(proj_tf32,
                         cudaFuncAttributeMaxDynamicSharedMemorySize, proj_smem);
    int score_smem = 2 * 128 * 68 * (int)sizeof(float);              // 69632
    cudaFuncSetAttribute(score_tf32,
                         cudaFuncAttributeMaxDynamicSharedMemorySize, score_smem);
    int av_smem = 3 * (128*36 + 32*72) * (int)sizeof(float);         // 82944
    cudaFuncSetAttribute(av_tf32,
                         cudaFuncAttributeMaxDynamicSharedMemorySize, av_smem);
    int smbytes = (12 * 1024 + 144 + 144 + 12 + 12) * (int)sizeof(float);
    cudaFuncSetAttribute(softmax_mix_kernel,
                         cudaFuncAttributeMaxDynamicSharedMemorySize, smbytes);

    // QKV projections -> [b,h,n,d]; Q pre-scaled
    proj_tf32<<<dim3(6, 64), 256, proj_smem>>>(x, Wq, gq, nullptr, scale, 1);
    proj_tf32<<<dim3(6, 64), 256, proj_smem>>>(x, Wk, gk, nullptr, 1.0f, 1);
    proj_tf32<<<dim3(6, 64), 256, proj_smem>>>(x, Wv, gv, nullptr, 1.0f, 1);

    // raw scores S = Q K^T
    score_tf32<<<dim3(8, 8, 96), 256, score_smem>>>(gq, gk, gS);

    // fused pre-mix + softmax + post-mix (in place on gS)
    softmax_mix_kernel<<<dim3(1024, 8), 384, smbytes>>>(gS, Wl, bl, Ww, bw);

    // attn @ V -> [tok, dim]
    av_tf32<<<dim3(8, 96), 256, av_smem>>>(gS, gv, gO);

    // final projection + bias
    proj_tf32<<<dim3(6, 64), 256, proj_smem>>>(gO, Wp, out, bp, 1.0f, 0);
}